// round 11
// baseline (speedup 1.0000x reference)
#include <cuda_runtime.h>
#include <cuda_bf16.h>
#include <cstdint>

#define BB 128
#define SS 128
#define NN 784
#define DD 512
#define NT 112
#define N_ITERS 10
#define EPS_F 2.2204460492503131e-16f
#define QF (1.0f / 784.0f)
#define PF (1.0f / 128.0f)

// ---------------- device scratch ----------------
__device__ float g_K[(size_t)BB * SS * NN];          // 51.4 MB
__device__ __nv_bfloat16 g_thi[SS * DD];             // normalized target, bf16 hi
__device__ __nv_bfloat16 g_tlo[SS * DD];             // residual lo

// ---------------- helpers ----------------
__device__ __forceinline__ uint32_t smem_u32(const void* p) {
    uint32_t a;
    asm("{ .reg .u64 t; cvta.to.shared.u64 t, %1; cvt.u32.u64 %0, t; }" : "=r"(a) : "l"(p));
    return a;
}
__device__ __forceinline__ unsigned short bf_bits(__nv_bfloat16 h) {
    return *reinterpret_cast<unsigned short*>(&h);
}
__device__ __forceinline__ void ldm_x4(uint32_t* r, uint32_t addr) {
    asm volatile("ldmatrix.sync.aligned.m8n8.x4.shared.b16 {%0,%1,%2,%3}, [%4];"
                 : "=r"(r[0]), "=r"(r[1]), "=r"(r[2]), "=r"(r[3]) : "r"(addr));
}
__device__ __forceinline__ void ldm_x2(uint32_t* r, uint32_t addr) {
    asm volatile("ldmatrix.sync.aligned.m8n8.x2.shared.b16 {%0,%1}, [%2];"
                 : "=r"(r[0]), "=r"(r[1]) : "r"(addr));
}
__device__ __forceinline__ void mma16816(float* c, const uint32_t* a, const uint32_t* b) {
    asm volatile("mma.sync.aligned.m16n8k16.row.col.f32.bf16.bf16.f32 "
                 "{%0,%1,%2,%3}, {%4,%5,%6,%7}, {%8,%9}, {%0,%1,%2,%3};"
                 : "+f"(c[0]), "+f"(c[1]), "+f"(c[2]), "+f"(c[3])
                 : "r"(a[0]), "r"(a[1]), "r"(a[2]), "r"(a[3]), "r"(b[0]), "r"(b[1]));
}
#define CP16(dst, src) \
    asm volatile("cp.async.cg.shared.global [%0], [%1], 16;" :: "r"(dst), "l"(src))
#define CP_COMMIT() asm volatile("cp.async.commit_group;")
#define CP_WAIT0()  asm volatile("cp.async.wait_group 0;")

#define CLUSTER_SYNC() do { \
    asm volatile("barrier.cluster.arrive.aligned;" ::: "memory"); \
    asm volatile("barrier.cluster.wait.aligned;" ::: "memory"); \
} while (0)

// ---------------- kernel 1: normalize target + split hi/lo bf16 ----------------
__global__ void norm_target_kernel(const float* __restrict__ t) {
    int s = blockIdx.x;
    int tid = threadIdx.x;  // 128 threads, 4 cols each
    __shared__ float red[4];
    const float4* tr = (const float4*)(t + (size_t)s * DD);
    float4 v = tr[tid];
    float ss = v.x * v.x + v.y * v.y + v.z * v.z + v.w * v.w;
    #pragma unroll
    for (int o = 16; o; o >>= 1) ss += __shfl_xor_sync(0xffffffffu, ss, o);
    if ((tid & 31) == 0) red[tid >> 5] = ss;
    __syncthreads();
    float inv = rsqrtf(red[0] + red[1] + red[2] + red[3]);

    float x[4] = {v.x * inv, v.y * inv, v.z * inv, v.w * inv};
    unsigned short h[4], l[4];
    #pragma unroll
    for (int i = 0; i < 4; i++) {
        __nv_bfloat16 hb = __float2bfloat16(x[i]);
        h[i] = bf_bits(hb);
        l[i] = bf_bits(__float2bfloat16(x[i] - __bfloat162float(hb)));
    }
    *(ushort4*)&g_thi[s * DD + tid * 4] = make_ushort4(h[0], h[1], h[2], h[3]);
    *(ushort4*)&g_tlo[s * DD + tid * 4] = make_ushort4(l[0], l[1], l[2], l[3]);
}

// ---------------- kernel 2: split-bf16 mma.sync GEMM + exp epilogue ----------------
// D[s,n] = sum_k tn[s,k]*fn[n,k] via hh + lh + hl, then K = exp(20*D - 20)
#define KC   64
#define LDA  72            // bf16 elements per smem row (64 + 8 pad)
#define OF_RN 0            // 448 B
#define OF_AH 512
#define OF_AL (OF_AH + 128 * LDA * 2)   // +18432
#define OF_BH (OF_AL + 128 * LDA * 2)
#define OF_BL (OF_BH + NT * LDA * 2)    // +16128
#define GEMM_SMEM (OF_BL + NT * LDA * 2)

__global__ __launch_bounds__(256, 2) void gemm_mma_kernel(const float* __restrict__ f) {
    extern __shared__ unsigned char smem[];
    const int b   = blockIdx.y;
    const int n0  = blockIdx.x * NT;
    const int tid = threadIdx.x;
    const int wid  = tid >> 5;
    const int lane = tid & 31;
    const int sgrp = wid & 3;          // S block of 32
    const int ngrp = wid >> 2;         // N block of 56
    uint32_t sb = smem_u32(smem);
    float* rn_s = (float*)(smem + OF_RN);

    const float* fb = f + (size_t)b * NN * DD;

    // prologue: inverse norms of this CTA's 112 feature rows (one warp per row)
    for (int r = wid; r < NT; r += 8) {
        const float4* fr = (const float4*)(fb + (size_t)(n0 + r) * DD);
        float ssum = 0.f;
        #pragma unroll
        for (int i = lane; i < DD / 4; i += 32) {
            float4 v = fr[i];
            ssum += v.x * v.x + v.y * v.y + v.z * v.z + v.w * v.w;
        }
        #pragma unroll
        for (int o = 16; o; o >>= 1) ssum += __shfl_xor_sync(0xffffffffu, ssum, o);
        if (lane == 0) rn_s[r] = rsqrtf(ssum);
    }
    __syncthreads();

    float acc[2][7][4];
    #pragma unroll
    for (int mt = 0; mt < 2; mt++)
        #pragma unroll
        for (int nt = 0; nt < 7; nt++)
            #pragma unroll
            for (int i = 0; i < 4; i++) acc[mt][nt][i] = 0.f;

    for (int c = 0; c < 8; ++c) {
        if (c) __syncthreads();     // previous chunk fully consumed

        // A tiles: cp.async pre-split bf16 hi/lo (L2-resident, 128 x 64)
        #pragma unroll
        for (int i = tid; i < 1024; i += 256) {
            int s = i >> 3, seg = i & 7;
            int go = s * DD + c * KC + seg * 8;
            uint32_t so = (s * LDA + seg * 8) * 2;
            CP16(sb + OF_AH + so, g_thi + go);
            CP16(sb + OF_AL + so, g_tlo + go);
        }
        CP_COMMIT();

        // B tiles: load f32 features, fold rn, split, STS
        for (int u = tid; u < NT * 8; u += 256) {
            int r = u >> 3, seg = u & 7;
            const float4* src = (const float4*)(fb + (size_t)(n0 + r) * DD + c * KC + seg * 8);
            float4 v0 = src[0], v1 = src[1];
            float rr = rn_s[r];
            float x[8] = {v0.x * rr, v0.y * rr, v0.z * rr, v0.w * rr,
                          v1.x * rr, v1.y * rr, v1.z * rr, v1.w * rr};
            uint32_t H[4], L[4];
            #pragma unroll
            for (int i = 0; i < 4; i++) {
                __nv_bfloat16 h0 = __float2bfloat16(x[2 * i]);
                __nv_bfloat16 h1 = __float2bfloat16(x[2 * i + 1]);
                __nv_bfloat16 l0 = __float2bfloat16(x[2 * i] - __bfloat162float(h0));
                __nv_bfloat16 l1 = __float2bfloat16(x[2 * i + 1] - __bfloat162float(h1));
                H[i] = (uint32_t)bf_bits(h0) | ((uint32_t)bf_bits(h1) << 16);
                L[i] = (uint32_t)bf_bits(l0) | ((uint32_t)bf_bits(l1) << 16);
            }
            uint32_t so = (r * LDA + seg * 8) * 2;
            *(uint4*)(smem + OF_BH + so) = make_uint4(H[0], H[1], H[2], H[3]);
            *(uint4*)(smem + OF_BL + so) = make_uint4(L[0], L[1], L[2], L[3]);
        }
        CP_WAIT0();
        __syncthreads();

        // compute: 4 k-steps of 16
        const int arow = sgrp * 32 + (lane & 15);
        const int acol = (lane >> 4) * 8;
        const int l2 = lane & 15;
        const int bcol = (lane >> 4) * 8;   // threads 16-31 fetch the k+8 half
        #pragma unroll
        for (int ks = 0; ks < 4; ks++) {
            const int kk = ks * 16;
            uint32_t ah[2][4], al[2][4], bf[7][2];
            #pragma unroll
            for (int mt = 0; mt < 2; mt++) {
                uint32_t ao = ((arow + mt * 16) * LDA + kk + acol) * 2;
                ldm_x4(ah[mt], sb + OF_AH + ao);
                ldm_x4(al[mt], sb + OF_AL + ao);
            }
            // B hi fragments: 3 pairs via x4 + 1 via x2
            #pragma unroll
            for (int p = 0; p < 3; p++) {
                uint32_t r4[4];
                ldm_x4(r4, sb + OF_BH + ((ngrp * 56 + p * 16 + l2) * LDA + kk + bcol) * 2);
                bf[2 * p][0] = r4[0]; bf[2 * p][1] = r4[2];
                bf[2 * p + 1][0] = r4[1]; bf[2 * p + 1][1] = r4[3];
            }
            ldm_x2(bf[6], sb + OF_BH + ((ngrp * 56 + 48 + (l2 & 7)) * LDA + kk + (l2 >> 3) * 8) * 2);
            #pragma unroll
            for (int mt = 0; mt < 2; mt++)
                #pragma unroll
                for (int nt = 0; nt < 7; nt++) {
                    mma16816(acc[mt][nt], ah[mt], bf[nt]);   // hi*hi
                    mma16816(acc[mt][nt], al[mt], bf[nt]);   // lo*hi
                }
            // B lo fragments (reuse regs)
            #pragma unroll
            for (int p = 0; p < 3; p++) {
                uint32_t r4[4];
                ldm_x4(r4, sb + OF_BL + ((ngrp * 56 + p * 16 + l2) * LDA + kk + bcol) * 2);
                bf[2 * p][0] = r4[0]; bf[2 * p][1] = r4[2];
                bf[2 * p + 1][0] = r4[1]; bf[2 * p + 1][1] = r4[3];
            }
            ldm_x2(bf[6], sb + OF_BL + ((ngrp * 56 + 48 + (l2 & 7)) * LDA + kk + (l2 >> 3) * 8) * 2);
            #pragma unroll
            for (int mt = 0; mt < 2; mt++)
                #pragma unroll
                for (int nt = 0; nt < 7; nt++)
                    mma16816(acc[mt][nt], ah[mt], bf[nt]);   // hi*lo
        }
    }

    // epilogue: K = exp(20*acc - 20), direct store (rows contiguous in n)
    const int g = lane >> 2;
    const int t2 = (lane & 3) * 2;
    #pragma unroll
    for (int mt = 0; mt < 2; mt++) {
        int srow0 = sgrp * 32 + mt * 16 + g;
        float* kr0 = g_K + ((size_t)b * SS + srow0) * NN + n0 + ngrp * 56;
        float* kr1 = kr0 + 8 * NN;
        #pragma unroll
        for (int nt = 0; nt < 7; nt++) {
            int cc = nt * 8 + t2;
            kr0[cc]     = __expf(fmaf(acc[mt][nt][0], 20.f, -20.f));
            kr0[cc + 1] = __expf(fmaf(acc[mt][nt][1], 20.f, -20.f));
            kr1[cc]     = __expf(fmaf(acc[mt][nt][2], 20.f, -20.f));
            kr1[cc + 1] = __expf(fmaf(acc[mt][nt][3], 20.f, -20.f));
        }
    }
}

// ---------------- kernel 3: SMEM-resident Sinkhorn, 2-CTA cluster per batch ----------------
// Each CTA holds K[b][0:128][rank*392 : rank*392+392] in smem (200 KB), loaded ONCE.
// v-update: fully local column sums. u-update: local row partials + DSMEM exchange
// of 128 partials with peer CTA, one cluster.sync per iteration (parity mailbox).
#define HC 392                       // columns per CTA (NN/2)
#define KF   0                       // K tile: 50176 floats
#define APF  50176                   // Apart[392]
#define SVF  (APF + HC)              // sv[392]
#define SUF  (SVF + HC)              // su[128]
#define MLF  (SUF + 128)             // myloc[128]
#define MAF  (MLF + 128)             // mail[2][128]
#define SINK_FLOATS (MAF + 256)      // 51472 floats
#define SINK_SMEM (SINK_FLOATS * 4)  // 205888 B

__global__ void __cluster_dims__(2, 1, 1) __launch_bounds__(1024, 1)
sinkhorn_cluster_kernel(float* __restrict__ Pi) {
    extern __shared__ float sm[];
    float* Kt    = sm + KF;
    float* Apart = sm + APF;
    float* sv    = sm + SVF;
    float* su    = sm + SUF;
    float* myloc = sm + MLF;
    float* mail  = sm + MAF;

    const int tid  = threadIdx.x;
    const int warp = tid >> 5;
    const int lane = tid & 31;
    uint32_t rank;
    asm("mov.u32 %0, %%cluster_ctarank;" : "=r"(rank));
    const int b = blockIdx.x >> 1;
    const uint32_t sb = smem_u32(sm);

    // load my 128 x 392 half-tile of K (once)
    {
        const float* Kb = g_K + (size_t)b * SS * NN + rank * HC;
        for (int i = tid; i < 12544; i += 1024) {       // 98 float4 per row
            int s = i / 98, j = i - s * 98;
            CP16(sb + (uint32_t)(s * HC + j * 4) * 4, Kb + (size_t)s * NN + j * 4);
        }
        CP_COMMIT();
    }
    if (tid < SS) su[tid] = 1.0f;
    CP_WAIT0();
    __syncthreads();
    CLUSTER_SYNC();   // both CTAs ready before any DSMEM traffic

    // phase-1 mapping: 784 active threads = 2 groups x 392 columns, 64 rows each
    const int pg = (tid < 784) ? (tid / HC) : 0;
    const int pc = (tid < 784) ? (tid - pg * HC) : 0;

    for (int it = 0; it <= N_ITERS; it++) {
        // ---- phase 1: v[n] = q / (sum_s su[s] * K[s,n] + eps)  (local) ----
        float accv = 0.f;
        if (tid < 784) {
            const float* kc = Kt + pc;
            const int s0 = pg * 64;
            float a0 = 0.f, a1 = 0.f, a2 = 0.f, a3 = 0.f;
            #pragma unroll 4
            for (int s = 0; s < 64; s += 4) {
                a0 = fmaf(su[s0 + s + 0], kc[(s0 + s + 0) * HC], a0);
                a1 = fmaf(su[s0 + s + 1], kc[(s0 + s + 1) * HC], a1);
                a2 = fmaf(su[s0 + s + 2], kc[(s0 + s + 2) * HC], a2);
                a3 = fmaf(su[s0 + s + 3], kc[(s0 + s + 3) * HC], a3);
            }
            accv = (a0 + a1) + (a2 + a3);
            if (pg == 1) Apart[pc] = accv;
        }
        __syncthreads();
        if (tid < HC) sv[tid] = QF / ((accv + Apart[tid]) + EPS_F);
        __syncthreads();

        // preload v registers: lanes cover cols lane + 32k, k = 0..12 (k=12: lane<8)
        float vr[13];
        #pragma unroll
        for (int k = 0; k < 12; k++) vr[k] = sv[lane + 32 * k];
        vr[12] = (lane < 8) ? sv[384 + lane] : 0.f;

        if (it < N_ITERS) {
            // ---- phase 2: partial u over my half; exchange with peer ----
            const int par = it & 1;
            #pragma unroll
            for (int j = 0; j < 4; j++) {
                const int s = warp * 4 + j;
                const float* kr = Kt + s * HC;
                float a0 = 0.f, a1 = 0.f;
                #pragma unroll
                for (int k = 0; k < 12; k += 2) {
                    a0 = fmaf(vr[k],     kr[lane + 32 * k],        a0);
                    a1 = fmaf(vr[k + 1], kr[lane + 32 * (k + 1)],  a1);
                }
                if (lane < 8) a0 = fmaf(vr[12], kr[384 + lane], a0);
                float a = a0 + a1;
                #pragma unroll
                for (int o = 16; o; o >>= 1) a += __shfl_xor_sync(0xffffffffu, a, o);
                if (lane == 0) {
                    myloc[s] = a;
                    uint32_t maddr = sb + (uint32_t)(MAF + par * 128 + s) * 4;
                    asm volatile(
                        "{\n\t.reg .b32 ra;\n\t"
                        "mapa.shared::cluster.u32 ra, %0, %1;\n\t"
                        "st.shared::cluster.f32 [ra], %2;\n\t}"
                        :: "r"(maddr), "r"(rank ^ 1u), "f"(a) : "memory");
                }
            }
            CLUSTER_SYNC();
            if (tid < SS) su[tid] = PF / ((myloc[tid] + mail[par * 128 + tid]) + EPS_F);
            __syncthreads();
        } else {
            // ---- final: Pi[s, n] = su[s] * K[s,n] * v[n]  (my half) ----
            float* Pb = Pi + (size_t)b * SS * NN + rank * HC;
            #pragma unroll
            for (int j = 0; j < 4; j++) {
                const int s = warp * 4 + j;
                const float* kr = Kt + s * HC;
                float* pr = Pb + (size_t)s * NN;
                const float us = su[s];
                #pragma unroll
                for (int k = 0; k < 12; k++)
                    pr[lane + 32 * k] = us * kr[lane + 32 * k] * vr[k];
                if (lane < 8) pr[384 + lane] = us * kr[384 + lane] * vr[12];
            }
        }
    }
}

// ---------------- launcher ----------------
extern "C" void kernel_launch(void* const* d_in, const int* in_sizes, int n_in,
                              void* d_out, int out_size) {
    const float* features = (const float*)d_in[0];
    const float* target   = (const float*)d_in[1];
    if (n_in >= 2 && in_sizes[0] == SS * DD) {
        const float* tmp = features; features = target; target = tmp;
    }
    float* Pi = (float*)d_out;

    cudaFuncSetAttribute(gemm_mma_kernel,
                         cudaFuncAttributeMaxDynamicSharedMemorySize, GEMM_SMEM);
    cudaFuncSetAttribute(sinkhorn_cluster_kernel,
                         cudaFuncAttributeMaxDynamicSharedMemorySize, SINK_SMEM);

    norm_target_kernel<<<SS, 128>>>(target);
    gemm_mma_kernel<<<dim3(7, BB), 256, GEMM_SMEM>>>(features);
    sinkhorn_cluster_kernel<<<2 * BB, 1024, SINK_SMEM>>>(Pi);
}

// round 12
// speedup vs baseline: 1.6038x; 1.6038x over previous
#include <cuda_runtime.h>
#include <cuda_bf16.h>
#include <cstdint>

#define BB 128
#define SS 128
#define NN 784
#define DD 512
#define NT 112
#define N_ITERS 10
#define EPS_F 2.2204460492503131e-16f
#define QF (1.0f / 784.0f)
#define PF (1.0f / 128.0f)

// ---------------- device scratch ----------------
__device__ float g_K[(size_t)BB * SS * NN];          // 51.4 MB
__device__ __nv_bfloat16 g_thi[SS * DD];             // normalized target, bf16 hi
__device__ __nv_bfloat16 g_tlo[SS * DD];             // residual lo

// ---------------- helpers ----------------
__device__ __forceinline__ uint32_t smem_u32(const void* p) {
    uint32_t a;
    asm("{ .reg .u64 t; cvta.to.shared.u64 t, %1; cvt.u32.u64 %0, t; }" : "=r"(a) : "l"(p));
    return a;
}
__device__ __forceinline__ unsigned short bf_bits(__nv_bfloat16 h) {
    return *reinterpret_cast<unsigned short*>(&h);
}
__device__ __forceinline__ void ldm_x4(uint32_t* r, uint32_t addr) {
    asm volatile("ldmatrix.sync.aligned.m8n8.x4.shared.b16 {%0,%1,%2,%3}, [%4];"
                 : "=r"(r[0]), "=r"(r[1]), "=r"(r[2]), "=r"(r[3]) : "r"(addr));
}
__device__ __forceinline__ void ldm_x2(uint32_t* r, uint32_t addr) {
    asm volatile("ldmatrix.sync.aligned.m8n8.x2.shared.b16 {%0,%1}, [%2];"
                 : "=r"(r[0]), "=r"(r[1]) : "r"(addr));
}
__device__ __forceinline__ void mma16816(float* c, const uint32_t* a, const uint32_t* b) {
    asm volatile("mma.sync.aligned.m16n8k16.row.col.f32.bf16.bf16.f32 "
                 "{%0,%1,%2,%3}, {%4,%5,%6,%7}, {%8,%9}, {%0,%1,%2,%3};"
                 : "+f"(c[0]), "+f"(c[1]), "+f"(c[2]), "+f"(c[3])
                 : "r"(a[0]), "r"(a[1]), "r"(a[2]), "r"(a[3]), "r"(b[0]), "r"(b[1]));
}
#define CP16(dst, src) \
    asm volatile("cp.async.cg.shared.global [%0], [%1], 16;" :: "r"(dst), "l"(src))
#define CP_COMMIT() asm volatile("cp.async.commit_group;")
#define CP_WAIT0()  asm volatile("cp.async.wait_group 0;")
#define CP_WAIT1()  asm volatile("cp.async.wait_group 1;")

// ---------------- kernel 1: normalize target + split hi/lo bf16 ----------------
__global__ void norm_target_kernel(const float* __restrict__ t) {
    int s = blockIdx.x;
    int tid = threadIdx.x;  // 128 threads, 4 cols each
    __shared__ float red[4];
    const float4* tr = (const float4*)(t + (size_t)s * DD);
    float4 v = tr[tid];
    float ss = v.x * v.x + v.y * v.y + v.z * v.z + v.w * v.w;
    #pragma unroll
    for (int o = 16; o; o >>= 1) ss += __shfl_xor_sync(0xffffffffu, ss, o);
    if ((tid & 31) == 0) red[tid >> 5] = ss;
    __syncthreads();
    float inv = rsqrtf(red[0] + red[1] + red[2] + red[3]);

    float x[4] = {v.x * inv, v.y * inv, v.z * inv, v.w * inv};
    unsigned short h[4], l[4];
    #pragma unroll
    for (int i = 0; i < 4; i++) {
        __nv_bfloat16 hb = __float2bfloat16(x[i]);
        h[i] = bf_bits(hb);
        l[i] = bf_bits(__float2bfloat16(x[i] - __bfloat162float(hb)));
    }
    *(ushort4*)&g_thi[s * DD + tid * 4] = make_ushort4(h[0], h[1], h[2], h[3]);
    *(ushort4*)&g_tlo[s * DD + tid * 4] = make_ushort4(l[0], l[1], l[2], l[3]);
}

// ---------------- kernel 2: pipelined split-bf16 mma.sync GEMM + exp epilogue ----------------
// acc[s,n] = dot(tn[s], f_raw[n]) via hh + lh + hl;  K = exp(20*acc*rn[n] - 20)
// rn computed on the fly from sums of squares accumulated during conversion.
#define KC   64
#define LDA  72            // bf16 elements per smem row (64 + 8 pad)
#define OF_RN  0                         // 112 floats
#define OF_SSQ 448                       // 896 floats
#define OF_STG 4032                      // 7168 floats f32 staging (28672 B)
#define OF_AH  32704                     // 128*LDA bf16 (18432 B)
#define OF_AL  (OF_AH + 128 * LDA * 2)
#define OF_BH  (OF_AL + 128 * LDA * 2)
#define OF_BL  (OF_BH + NT * LDA * 2)
#define GEMM_SMEM (OF_BL + NT * LDA * 2) // 101824 B -> 2 CTAs/SM

__global__ __launch_bounds__(256, 2) void gemm_mma_kernel(const float* __restrict__ f) {
    extern __shared__ unsigned char smem[];
    const int b   = blockIdx.y;
    const int n0  = blockIdx.x * NT;
    const int tid = threadIdx.x;
    const int wid  = tid >> 5;
    const int lane = tid & 31;
    const int sgrp = wid & 3;          // S block of 32
    const int ngrp = wid >> 2;         // N block of 56
    uint32_t sb = smem_u32(smem);
    float* rn_s = (float*)(smem + OF_RN);
    float* ssqp = (float*)(smem + OF_SSQ);

    const float* fb = f + (size_t)b * NN * DD;

    // stage raw f32 B-tile for chunk c into thread-private staging slots
    auto stage_B = [&](int c) {
        #pragma unroll
        for (int i = 0; i < 4; i++) {
            int u = tid + i * 256;
            if (i == 3 && tid >= 128) break;
            int r = u >> 3, seg = u & 7;
            const float* src = fb + (size_t)(n0 + r) * DD + c * KC + seg * 8;
            uint32_t dst = sb + OF_STG + (uint32_t)u * 32;
            CP16(dst, src);
            CP16(dst + 16, src + 4);
        }
        CP_COMMIT();
    };

    float acc[2][7][4];
    #pragma unroll
    for (int mt = 0; mt < 2; mt++)
        #pragma unroll
        for (int nt = 0; nt < 7; nt++)
            #pragma unroll
            for (int i = 0; i < 4; i++) acc[mt][nt][i] = 0.f;

    float ssq_acc[4] = {0.f, 0.f, 0.f, 0.f};

    stage_B(0);

    for (int c = 0; c < 8; ++c) {
        __syncthreads();            // bf16 bufs free (compute of c-1 done)
        CP_WAIT0();                 // staging(c) resident

        // A tiles: cp.async pre-split bf16 hi/lo (L2 resident)
        #pragma unroll
        for (int i = tid; i < 1024; i += 256) {
            int s = i >> 3, seg = i & 7;
            int go = s * DD + c * KC + seg * 8;
            uint32_t so = (s * LDA + seg * 8) * 2;
            CP16(sb + OF_AH + so, g_thi + go);
            CP16(sb + OF_AL + so, g_tlo + go);
        }
        CP_COMMIT();                // group GA

        // convert staging(c): raw f32 -> bf16 hi/lo, accumulate sum of squares
        #pragma unroll
        for (int i = 0; i < 4; i++) {
            int u = tid + i * 256;
            if (i == 3 && tid >= 128) break;
            int r = u >> 3, seg = u & 7;
            const float4* s4 = (const float4*)(smem + OF_STG + (uint32_t)u * 32);
            float4 v0 = s4[0], v1 = s4[1];
            float x[8] = {v0.x, v0.y, v0.z, v0.w, v1.x, v1.y, v1.z, v1.w};
            float sq = 0.f;
            #pragma unroll
            for (int k = 0; k < 8; k++) sq = fmaf(x[k], x[k], sq);
            ssq_acc[i] += sq;
            uint32_t H[4], L[4];
            #pragma unroll
            for (int k = 0; k < 4; k++) {
                __nv_bfloat16 h0 = __float2bfloat16(x[2 * k]);
                __nv_bfloat16 h1 = __float2bfloat16(x[2 * k + 1]);
                __nv_bfloat16 l0 = __float2bfloat16(x[2 * k] - __bfloat162float(h0));
                __nv_bfloat16 l1 = __float2bfloat16(x[2 * k + 1] - __bfloat162float(h1));
                H[k] = (uint32_t)bf_bits(h0) | ((uint32_t)bf_bits(h1) << 16);
                L[k] = (uint32_t)bf_bits(l0) | ((uint32_t)bf_bits(l1) << 16);
            }
            uint32_t so = (r * LDA + seg * 8) * 2;
            *(uint4*)(smem + OF_BH + so) = make_uint4(H[0], H[1], H[2], H[3]);
            *(uint4*)(smem + OF_BL + so) = make_uint4(L[0], L[1], L[2], L[3]);
        }

        // prefetch next chunk's raw B (stays in flight through compute)
        if (c < 7) { stage_B(c + 1); CP_WAIT1(); }
        else       { CP_WAIT0(); }
        __syncthreads();            // A + B bf16 tiles ready

        // compute: 4 k-steps of 16
        const int arow = sgrp * 32 + (lane & 15);
        const int acol = (lane >> 4) * 8;
        const int l2 = lane & 15;
        const int bcol = (lane >> 4) * 8;
        #pragma unroll
        for (int ks = 0; ks < 4; ks++) {
            const int kk = ks * 16;
            uint32_t ah[2][4], al[2][4], bf[7][2];
            #pragma unroll
            for (int mt = 0; mt < 2; mt++) {
                uint32_t ao = ((arow + mt * 16) * LDA + kk + acol) * 2;
                ldm_x4(ah[mt], sb + OF_AH + ao);
                ldm_x4(al[mt], sb + OF_AL + ao);
            }
            #pragma unroll
            for (int p = 0; p < 3; p++) {
                uint32_t r4[4];
                ldm_x4(r4, sb + OF_BH + ((ngrp * 56 + p * 16 + l2) * LDA + kk + bcol) * 2);
                bf[2 * p][0] = r4[0]; bf[2 * p][1] = r4[2];
                bf[2 * p + 1][0] = r4[1]; bf[2 * p + 1][1] = r4[3];
            }
            ldm_x2(bf[6], sb + OF_BH + ((ngrp * 56 + 48 + (l2 & 7)) * LDA + kk + (l2 >> 3) * 8) * 2);
            #pragma unroll
            for (int mt = 0; mt < 2; mt++)
                #pragma unroll
                for (int nt = 0; nt < 7; nt++) {
                    mma16816(acc[mt][nt], ah[mt], bf[nt]);   // hi*hi
                    mma16816(acc[mt][nt], al[mt], bf[nt]);   // lo*hi
                }
            #pragma unroll
            for (int p = 0; p < 3; p++) {
                uint32_t r4[4];
                ldm_x4(r4, sb + OF_BL + ((ngrp * 56 + p * 16 + l2) * LDA + kk + bcol) * 2);
                bf[2 * p][0] = r4[0]; bf[2 * p][1] = r4[2];
                bf[2 * p + 1][0] = r4[1]; bf[2 * p + 1][1] = r4[3];
            }
            ldm_x2(bf[6], sb + OF_BL + ((ngrp * 56 + 48 + (l2 & 7)) * LDA + kk + (l2 >> 3) * 8) * 2);
            #pragma unroll
            for (int mt = 0; mt < 2; mt++)
                #pragma unroll
                for (int nt = 0; nt < 7; nt++)
                    mma16816(acc[mt][nt], ah[mt], bf[nt]);   // hi*lo
        }
    }

    // rn from accumulated sums of squares
    __syncthreads();
    #pragma unroll
    for (int i = 0; i < 4; i++) {
        int u = tid + i * 256;
        if (i == 3 && tid >= 128) break;
        ssqp[u] = ssq_acc[i];
    }
    __syncthreads();
    if (tid < NT) {
        float a = 0.f;
        #pragma unroll
        for (int seg = 0; seg < 8; seg++) a += ssqp[tid * 8 + seg];
        rn_s[tid] = rsqrtf(a);
    }
    __syncthreads();

    // epilogue: K = exp(20*acc*rn - 20)
    const int g = lane >> 2;
    const int t2 = (lane & 3) * 2;
    #pragma unroll
    for (int mt = 0; mt < 2; mt++) {
        int srow0 = sgrp * 32 + mt * 16 + g;
        float* kr0 = g_K + ((size_t)b * SS + srow0) * NN + n0 + ngrp * 56;
        float* kr1 = kr0 + 8 * NN;
        #pragma unroll
        for (int nt = 0; nt < 7; nt++) {
            int cc = nt * 8 + t2;
            float s0 = 20.f * rn_s[ngrp * 56 + cc];
            float s1 = 20.f * rn_s[ngrp * 56 + cc + 1];
            kr0[cc]     = __expf(fmaf(acc[mt][nt][0], s0, -20.f));
            kr0[cc + 1] = __expf(fmaf(acc[mt][nt][1], s1, -20.f));
            kr1[cc]     = __expf(fmaf(acc[mt][nt][2], s0, -20.f));
            kr1[cc + 1] = __expf(fmaf(acc[mt][nt][3], s1, -20.f));
        }
    }
}

// ---------------- kernel 3: Sinkhorn + Pi, one CTA per batch (proven R9 version) ----------------
__global__ __launch_bounds__(1024, 1) void sinkhorn_kernel(float* __restrict__ Pi) {
    const int b = blockIdx.x;
    const int tid = threadIdx.x;
    const int warp = tid >> 5;
    const int lane = tid & 31;
    const float* __restrict__ Kb = g_K + (size_t)b * SS * NN;

    __shared__ float su[SS];
    __shared__ float sv[NN];
    if (tid < SS) su[tid] = 1.0f;
    __syncthreads();

    for (int it = 0; it < N_ITERS; it++) {
        if (tid < NN) {
            const float* Kc = Kb + tid;
            float a0 = 0.f, a1 = 0.f, a2 = 0.f, a3 = 0.f;
            #pragma unroll 8
            for (int s = 0; s < SS; s += 4) {
                a0 = fmaf(su[s + 0], Kc[(size_t)(s + 0) * NN], a0);
                a1 = fmaf(su[s + 1], Kc[(size_t)(s + 1) * NN], a1);
                a2 = fmaf(su[s + 2], Kc[(size_t)(s + 2) * NN], a2);
                a3 = fmaf(su[s + 3], Kc[(size_t)(s + 3) * NN], a3);
            }
            sv[tid] = QF / (((a0 + a1) + (a2 + a3)) + EPS_F);
        }
        __syncthreads();
        for (int s = warp; s < SS; s += 32) {
            const float* Kr = Kb + (size_t)s * NN;
            float a0 = 0.f, a1 = 0.f;
            for (int n = lane; n < NN; n += 64) {
                a0 = fmaf(sv[n], Kr[n], a0);
                int n2 = n + 32;
                if (n2 < NN) a1 = fmaf(sv[n2], Kr[n2], a1);
            }
            float a = a0 + a1;
            #pragma unroll
            for (int o = 16; o; o >>= 1) a += __shfl_xor_sync(0xffffffffu, a, o);
            if (lane == 0) su[s] = PF / (a + EPS_F);
        }
        __syncthreads();
    }

    if (tid < NN) {
        const float* Kc = Kb + tid;
        float a0 = 0.f, a1 = 0.f, a2 = 0.f, a3 = 0.f;
        #pragma unroll 8
        for (int s = 0; s < SS; s += 4) {
            a0 = fmaf(su[s + 0], Kc[(size_t)(s + 0) * NN], a0);
            a1 = fmaf(su[s + 1], Kc[(size_t)(s + 1) * NN], a1);
            a2 = fmaf(su[s + 2], Kc[(size_t)(s + 2) * NN], a2);
            a3 = fmaf(su[s + 3], Kc[(size_t)(s + 3) * NN], a3);
        }
        sv[tid] = QF / (((a0 + a1) + (a2 + a3)) + EPS_F);
    }
    __syncthreads();

    if (tid < NN) {
        float vv = sv[tid];
        const float* Kc = Kb + tid;
        float* Pc = Pi + (size_t)b * SS * NN + tid;
        #pragma unroll 4
        for (int s = 0; s < SS; s++)
            Pc[(size_t)s * NN] = su[s] * Kc[(size_t)s * NN] * vv;
    }
}

// ---------------- launcher ----------------
extern "C" void kernel_launch(void* const* d_in, const int* in_sizes, int n_in,
                              void* d_out, int out_size) {
    const float* features = (const float*)d_in[0];
    const float* target   = (const float*)d_in[1];
    if (n_in >= 2 && in_sizes[0] == SS * DD) {
        const float* tmp = features; features = target; target = tmp;
    }
    float* Pi = (float*)d_out;

    cudaFuncSetAttribute(gemm_mma_kernel,
                         cudaFuncAttributeMaxDynamicSharedMemorySize, GEMM_SMEM);

    norm_target_kernel<<<SS, 128>>>(target);
    gemm_mma_kernel<<<dim3(7, BB), 256, GEMM_SMEM>>>(features);
    sinkhorn_kernel<<<BB, 1024>>>(Pi);
}

// round 15
// speedup vs baseline: 1.7224x; 1.0740x over previous
#include <cuda_runtime.h>
#include <cuda_bf16.h>
#include <cstdint>

#define BB 128
#define SS 128
#define NN 784
#define DD 512
#define NT 112
#define N_ITERS 10
#define EPS_F 2.2204460492503131e-16f
#define QF (1.0f / 784.0f)
#define PF (1.0f / 128.0f)

// ---------------- device scratch ----------------
__device__ float g_K[(size_t)BB * SS * NN];          // 51.4 MB
__device__ __nv_bfloat16 g_thi[SS * DD];             // normalized target, bf16 hi
__device__ __nv_bfloat16 g_tlo[SS * DD];             // residual lo

// ---------------- helpers ----------------
__device__ __forceinline__ uint32_t smem_u32(const void* p) {
    uint32_t a;
    asm("{ .reg .u64 t; cvta.to.shared.u64 t, %1; cvt.u32.u64 %0, t; }" : "=r"(a) : "l"(p));
    return a;
}
__device__ __forceinline__ unsigned short bf_bits(__nv_bfloat16 h) {
    return *reinterpret_cast<unsigned short*>(&h);
}
__device__ __forceinline__ void ldm_x4(uint32_t* r, uint32_t addr) {
    asm volatile("ldmatrix.sync.aligned.m8n8.x4.shared.b16 {%0,%1,%2,%3}, [%4];"
                 : "=r"(r[0]), "=r"(r[1]), "=r"(r[2]), "=r"(r[3]) : "r"(addr));
}
__device__ __forceinline__ void ldm_x2(uint32_t* r, uint32_t addr) {
    asm volatile("ldmatrix.sync.aligned.m8n8.x2.shared.b16 {%0,%1}, [%2];"
                 : "=r"(r[0]), "=r"(r[1]) : "r"(addr));
}
__device__ __forceinline__ void mma16816(float* c, const uint32_t* a, const uint32_t* b) {
    asm volatile("mma.sync.aligned.m16n8k16.row.col.f32.bf16.bf16.f32 "
                 "{%0,%1,%2,%3}, {%4,%5,%6,%7}, {%8,%9}, {%0,%1,%2,%3};"
                 : "+f"(c[0]), "+f"(c[1]), "+f"(c[2]), "+f"(c[3])
                 : "r"(a[0]), "r"(a[1]), "r"(a[2]), "r"(a[3]), "r"(b[0]), "r"(b[1]));
}
#define CP16(dst, src) \
    asm volatile("cp.async.cg.shared.global [%0], [%1], 16;" :: "r"(dst), "l"(src))
#define CP_COMMIT() asm volatile("cp.async.commit_group;")
#define CP_WAIT0()  asm volatile("cp.async.wait_group 0;")
#define CP_WAIT1()  asm volatile("cp.async.wait_group 1;")

// ---------------- kernel 1: normalize target + split hi/lo bf16 ----------------
__global__ void norm_target_kernel(const float* __restrict__ t) {
    int s = blockIdx.x;
    int tid = threadIdx.x;  // 128 threads, 4 cols each
    __shared__ float red[4];
    const float4* tr = (const float4*)(t + (size_t)s * DD);
    float4 v = tr[tid];
    float ss = v.x * v.x + v.y * v.y + v.z * v.z + v.w * v.w;
    #pragma unroll
    for (int o = 16; o; o >>= 1) ss += __shfl_xor_sync(0xffffffffu, ss, o);
    if ((tid & 31) == 0) red[tid >> 5] = ss;
    __syncthreads();
    float inv = rsqrtf(red[0] + red[1] + red[2] + red[3]);

    float x[4] = {v.x * inv, v.y * inv, v.z * inv, v.w * inv};
    unsigned short h[4], l[4];
    #pragma unroll
    for (int i = 0; i < 4; i++) {
        __nv_bfloat16 hb = __float2bfloat16(x[i]);
        h[i] = bf_bits(hb);
        l[i] = bf_bits(__float2bfloat16(x[i] - __bfloat162float(hb)));
    }
    *(ushort4*)&g_thi[s * DD + tid * 4] = make_ushort4(h[0], h[1], h[2], h[3]);
    *(ushort4*)&g_tlo[s * DD + tid * 4] = make_ushort4(l[0], l[1], l[2], l[3]);
}

// ---------------- kernel 2: pipelined split-bf16 mma.sync GEMM + exp epilogue ----------------
// acc[s,n] = dot(tn[s], f_raw[n]) via hh + lh + hl;  K = exp(20*acc*rn[n] - 20)
#define KC   64
#define LDA  72            // bf16 elements per smem row (64 + 8 pad)
#define OF_RN  0                         // 112 floats
#define OF_SSQ 448                       // 896 floats
#define OF_STG 4032                      // 7168 floats f32 staging (28672 B)
#define OF_AH  32704                     // 128*LDA bf16 (18432 B)
#define OF_AL  (OF_AH + 128 * LDA * 2)
#define OF_BH  (OF_AL + 128 * LDA * 2)
#define OF_BL  (OF_BH + NT * LDA * 2)
#define GEMM_SMEM (OF_BL + NT * LDA * 2) // 101824 B -> 2 CTAs/SM

__global__ __launch_bounds__(256, 2) void gemm_mma_kernel(const float* __restrict__ f) {
    extern __shared__ unsigned char smem[];
    const int b   = blockIdx.y;
    const int n0  = blockIdx.x * NT;
    const int tid = threadIdx.x;
    const int wid  = tid >> 5;
    const int lane = tid & 31;
    const int sgrp = wid & 3;          // S block of 32
    const int ngrp = wid >> 2;         // N block of 56
    uint32_t sb = smem_u32(smem);
    float* rn_s = (float*)(smem + OF_RN);
    float* ssqp = (float*)(smem + OF_SSQ);

    const float* fb = f + (size_t)b * NN * DD;

    auto stage_B = [&](int c) {
        #pragma unroll
        for (int i = 0; i < 4; i++) {
            int u = tid + i * 256;
            if (i == 3 && tid >= 128) break;
            int r = u >> 3, seg = u & 7;
            const float* src = fb + (size_t)(n0 + r) * DD + c * KC + seg * 8;
            uint32_t dst = sb + OF_STG + (uint32_t)u * 32;
            CP16(dst, src);
            CP16(dst + 16, src + 4);
        }
        CP_COMMIT();
    };

    float acc[2][7][4];
    #pragma unroll
    for (int mt = 0; mt < 2; mt++)
        #pragma unroll
        for (int nt = 0; nt < 7; nt++)
            #pragma unroll
            for (int i = 0; i < 4; i++) acc[mt][nt][i] = 0.f;

    float ssq_acc[4] = {0.f, 0.f, 0.f, 0.f};

    stage_B(0);

    for (int c = 0; c < 8; ++c) {
        __syncthreads();
        CP_WAIT0();

        #pragma unroll
        for (int i = tid; i < 1024; i += 256) {
            int s = i >> 3, seg = i & 7;
            int go = s * DD + c * KC + seg * 8;
            uint32_t so = (s * LDA + seg * 8) * 2;
            CP16(sb + OF_AH + so, g_thi + go);
            CP16(sb + OF_AL + so, g_tlo + go);
        }
        CP_COMMIT();

        #pragma unroll
        for (int i = 0; i < 4; i++) {
            int u = tid + i * 256;
            if (i == 3 && tid >= 128) break;
            int r = u >> 3, seg = u & 7;
            const float4* s4 = (const float4*)(smem + OF_STG + (uint32_t)u * 32);
            float4 v0 = s4[0], v1 = s4[1];
            float x[8] = {v0.x, v0.y, v0.z, v0.w, v1.x, v1.y, v1.z, v1.w};
            float sq = 0.f;
            #pragma unroll
            for (int k = 0; k < 8; k++) sq = fmaf(x[k], x[k], sq);
            ssq_acc[i] += sq;
            uint32_t H[4], L[4];
            #pragma unroll
            for (int k = 0; k < 4; k++) {
                __nv_bfloat16 h0 = __float2bfloat16(x[2 * k]);
                __nv_bfloat16 h1 = __float2bfloat16(x[2 * k + 1]);
                __nv_bfloat16 l0 = __float2bfloat16(x[2 * k] - __bfloat162float(h0));
                __nv_bfloat16 l1 = __float2bfloat16(x[2 * k + 1] - __bfloat162float(h1));
                H[k] = (uint32_t)bf_bits(h0) | ((uint32_t)bf_bits(h1) << 16);
                L[k] = (uint32_t)bf_bits(l0) | ((uint32_t)bf_bits(l1) << 16);
            }
            uint32_t so = (r * LDA + seg * 8) * 2;
            *(uint4*)(smem + OF_BH + so) = make_uint4(H[0], H[1], H[2], H[3]);
            *(uint4*)(smem + OF_BL + so) = make_uint4(L[0], L[1], L[2], L[3]);
        }

        if (c < 7) { stage_B(c + 1); CP_WAIT1(); }
        else       { CP_WAIT0(); }
        __syncthreads();

        const int arow = sgrp * 32 + (lane & 15);
        const int acol = (lane >> 4) * 8;
        const int l2 = lane & 15;
        const int bcol = (lane >> 4) * 8;
        #pragma unroll
        for (int ks = 0; ks < 4; ks++) {
            const int kk = ks * 16;
            uint32_t ah[2][4], al[2][4], bf[7][2];
            #pragma unroll
            for (int mt = 0; mt < 2; mt++) {
                uint32_t ao = ((arow + mt * 16) * LDA + kk + acol) * 2;
                ldm_x4(ah[mt], sb + OF_AH + ao);
                ldm_x4(al[mt], sb + OF_AL + ao);
            }
            #pragma unroll
            for (int p = 0; p < 3; p++) {
                uint32_t r4[4];
                ldm_x4(r4, sb + OF_BH + ((ngrp * 56 + p * 16 + l2) * LDA + kk + bcol) * 2);
                bf[2 * p][0] = r4[0]; bf[2 * p][1] = r4[2];
                bf[2 * p + 1][0] = r4[1]; bf[2 * p + 1][1] = r4[3];
            }
            ldm_x2(bf[6], sb + OF_BH + ((ngrp * 56 + 48 + (l2 & 7)) * LDA + kk + (l2 >> 3) * 8) * 2);
            #pragma unroll
            for (int mt = 0; mt < 2; mt++)
                #pragma unroll
                for (int nt = 0; nt < 7; nt++) {
                    mma16816(acc[mt][nt], ah[mt], bf[nt]);   // hi*hi
                    mma16816(acc[mt][nt], al[mt], bf[nt]);   // lo*hi
                }
            #pragma unroll
            for (int p = 0; p < 3; p++) {
                uint32_t r4[4];
                ldm_x4(r4, sb + OF_BL + ((ngrp * 56 + p * 16 + l2) * LDA + kk + bcol) * 2);
                bf[2 * p][0] = r4[0]; bf[2 * p][1] = r4[2];
                bf[2 * p + 1][0] = r4[1]; bf[2 * p + 1][1] = r4[3];
            }
            ldm_x2(bf[6], sb + OF_BL + ((ngrp * 56 + 48 + (l2 & 7)) * LDA + kk + (l2 >> 3) * 8) * 2);
            #pragma unroll
            for (int mt = 0; mt < 2; mt++)
                #pragma unroll
                for (int nt = 0; nt < 7; nt++)
                    mma16816(acc[mt][nt], ah[mt], bf[nt]);   // hi*lo
        }
    }

    // rn from accumulated sums of squares
    __syncthreads();
    #pragma unroll
    for (int i = 0; i < 4; i++) {
        int u = tid + i * 256;
        if (i == 3 && tid >= 128) break;
        ssqp[u] = ssq_acc[i];
    }
    __syncthreads();
    if (tid < NT) {
        float a = 0.f;
        #pragma unroll
        for (int seg = 0; seg < 8; seg++) a += ssqp[tid * 8 + seg];
        rn_s[tid] = rsqrtf(a);
    }
    __syncthreads();

    // epilogue: K = exp(20*acc*rn - 20)
    const int g = lane >> 2;
    const int t2 = (lane & 3) * 2;
    #pragma unroll
    for (int mt = 0; mt < 2; mt++) {
        int srow0 = sgrp * 32 + mt * 16 + g;
        float* kr0 = g_K + ((size_t)b * SS + srow0) * NN + n0 + ngrp * 56;
        float* kr1 = kr0 + 8 * NN;
        #pragma unroll
        for (int nt = 0; nt < 7; nt++) {
            int cc = nt * 8 + t2;
            float s0 = 20.f * rn_s[ngrp * 56 + cc];
            float s1 = 20.f * rn_s[ngrp * 56 + cc + 1];
            kr0[cc]     = __expf(fmaf(acc[mt][nt][0], s0, -20.f));
            kr0[cc + 1] = __expf(fmaf(acc[mt][nt][1], s1, -20.f));
            kr1[cc]     = __expf(fmaf(acc[mt][nt][2], s0, -20.f));
            kr1[cc + 1] = __expf(fmaf(acc[mt][nt][3], s1, -20.f));
        }
    }
}

// ---------------- kernel 3: hybrid smem/L2 Sinkhorn + Pi ----------------
// Rows 0..63 of K_b cached in smem (200 KB, loaded once); rows 64..127 read
// from L2 each pass. Same two-pass structure and summation order as before.
#define SK_ROWS 64
#define SK_FLOATS (SK_ROWS * NN)                       // 50176
#define SINK_SMEM ((SK_FLOATS + SS + NN) * 4)          // 204352 B

__global__ __launch_bounds__(1024, 1) void sinkhorn_kernel(float* __restrict__ Pi) {
    extern __shared__ float sm[];
    float* sK = sm;                  // [64][784]
    float* su = sm + SK_FLOATS;      // [128]
    float* sv = su + SS;             // [784]

    const int b = blockIdx.x;
    const int tid = threadIdx.x;
    const int warp = tid >> 5;
    const int lane = tid & 31;
    const float* __restrict__ Kb = g_K + (size_t)b * SS * NN;
    const uint32_t sb = smem_u32(sm);

    // one-time: cache rows 0..63 (contiguous 200 KB)
    for (int i = tid; i < SK_FLOATS / 4; i += 1024)
        CP16(sb + (uint32_t)i * 16, Kb + (size_t)i * 4);
    CP_COMMIT();
    if (tid < SS) su[tid] = 1.0f;
    CP_WAIT0();
    __syncthreads();

    for (int it = 0; it < N_ITERS; it++) {
        // v[n] = q / (sum_s su[s]*K[s,n] + eps): s<64 smem, s>=64 gmem
        if (tid < NN) {
            const float* Sc = sK + tid;
            const float* Kc = Kb + tid;
            float a0 = 0.f, a1 = 0.f, a2 = 0.f, a3 = 0.f;
            #pragma unroll 4
            for (int s = 0; s < SK_ROWS; s += 4) {
                a0 = fmaf(su[s + 0], Sc[(s + 0) * NN], a0);
                a1 = fmaf(su[s + 1], Sc[(s + 1) * NN], a1);
                a2 = fmaf(su[s + 2], Sc[(s + 2) * NN], a2);
                a3 = fmaf(su[s + 3], Sc[(s + 3) * NN], a3);
            }
            #pragma unroll 4
            for (int s = SK_ROWS; s < SS; s += 4) {
                a0 = fmaf(su[s + 0], Kc[(size_t)(s + 0) * NN], a0);
                a1 = fmaf(su[s + 1], Kc[(size_t)(s + 1) * NN], a1);
                a2 = fmaf(su[s + 2], Kc[(size_t)(s + 2) * NN], a2);
                a3 = fmaf(su[s + 3], Kc[(size_t)(s + 3) * NN], a3);
            }
            sv[tid] = QF / (((a0 + a1) + (a2 + a3)) + EPS_F);
        }
        __syncthreads();
        // u[s] = p / (sum_n sv[n]*K[s,n] + eps): warp w owns rows 4w..4w+3
        #pragma unroll
        for (int j = 0; j < 4; j++) {
            const int s = warp * 4 + j;
            const float* Kr = (s < SK_ROWS) ? (sK + s * NN) : (Kb + (size_t)s * NN);
            float a0 = 0.f, a1 = 0.f;
            for (int n = lane; n < NN; n += 64) {
                a0 = fmaf(sv[n], Kr[n], a0);
                int n2 = n + 32;
                if (n2 < NN) a1 = fmaf(sv[n2], Kr[n2], a1);
            }
            float a = a0 + a1;
            #pragma unroll
            for (int o = 16; o; o >>= 1) a += __shfl_xor_sync(0xffffffffu, a, o);
            if (lane == 0) su[s] = PF / (a + EPS_F);
        }
        __syncthreads();
    }

    // final v
    if (tid < NN) {
        const float* Sc = sK + tid;
        const float* Kc = Kb + tid;
        float a0 = 0.f, a1 = 0.f, a2 = 0.f, a3 = 0.f;
        #pragma unroll 4
        for (int s = 0; s < SK_ROWS; s += 4) {
            a0 = fmaf(su[s + 0], Sc[(s + 0) * NN], a0);
            a1 = fmaf(su[s + 1], Sc[(s + 1) * NN], a1);
            a2 = fmaf(su[s + 2], Sc[(s + 2) * NN], a2);
            a3 = fmaf(su[s + 3], Sc[(s + 3) * NN], a3);
        }
        #pragma unroll 4
        for (int s = SK_ROWS; s < SS; s += 4) {
            a0 = fmaf(su[s + 0], Kc[(size_t)(s + 0) * NN], a0);
            a1 = fmaf(su[s + 1], Kc[(size_t)(s + 1) * NN], a1);
            a2 = fmaf(su[s + 2], Kc[(size_t)(s + 2) * NN], a2);
            a3 = fmaf(su[s + 3], Kc[(size_t)(s + 3) * NN], a3);
        }
        sv[tid] = QF / (((a0 + a1) + (a2 + a3)) + EPS_F);
    }
    __syncthreads();

    // Pi[s,n] = su[s] * K[s,n] * v[n]
    if (tid < NN) {
        float vv = sv[tid];
        const float* Sc = sK + tid;
        const float* Kc = Kb + tid;
        float* Pc = Pi + (size_t)b * SS * NN + tid;
        #pragma unroll 4
        for (int s = 0; s < SK_ROWS; s++)
            Pc[(size_t)s * NN] = su[s] * Sc[s * NN] * vv;
        #pragma unroll 4
        for (int s = SK_ROWS; s < SS; s++)
            Pc[(size_t)s * NN] = su[s] * Kc[(size_t)s * NN] * vv;
    }
}

// ---------------- launcher ----------------
extern "C" void kernel_launch(void* const* d_in, const int* in_sizes, int n_in,
                              void* d_out, int out_size) {
    const float* features = (const float*)d_in[0];
    const float* target   = (const float*)d_in[1];
    if (n_in >= 2 && in_sizes[0] == SS * DD) {
        const float* tmp = features; features = target; target = tmp;
    }
    float* Pi = (float*)d_out;

    cudaFuncSetAttribute(gemm_mma_kernel,
                         cudaFuncAttributeMaxDynamicSharedMemorySize, GEMM_SMEM);
    cudaFuncSetAttribute(sinkhorn_kernel,
                         cudaFuncAttributeMaxDynamicSharedMemorySize, SINK_SMEM);

    norm_target_kernel<<<SS, 128>>>(target);
    gemm_mma_kernel<<<dim3(7, BB), 256, GEMM_SMEM>>>(features);
    sinkhorn_kernel<<<BB, 1024, SINK_SMEM>>>(Pi);
}